// round 13
// baseline (speedup 1.0000x reference)
#include <cuda_runtime.h>
#include <cstdint>

// Problem constants (fixed by the reference):
//   B=4, S=4096, D=2048, E=8, T=B*S=16384, C=T/E*1.25=2560, EC=E*C=20480
#define D_DIM    2048
#define T_TOK    16384
#define EC_ROWS  20480
#define EC_BLKS  (EC_ROWS / 8)   // 2560 blocks, 8 expert slots each (2 iters of 4)
#define T_BLKS   (T_TOK / 8)     // first 2048 blocks also cover 8 tokens' fallback

// Single-launch scatter: 512 threads = 4 row-engines of 128 lanes x 4 float4
// (measured-best copy shape), iterated twice per block -> 8 expert slots.
// Scalar index/flag loads for BOTH iterations are prefetched up front so the
// second iteration's dependent chain is pre-resolved. Padding slots
// (scatter_idx == T) are skipped before any row traffic. The first T_BLKS
// blocks also handle the x-fallback for 8 tokens (row copied only if
// dropped). Writer sets are disjoint and cover every output row.
__global__ __launch_bounds__(512) void moe_scatter_kernel(
    const float* __restrict__ expert_outputs,   // [EC, D]
    const float* __restrict__ x,                // [T, D]
    const float* __restrict__ route_prob_max,   // [T]
    const int*   __restrict__ scatter_idx,      // [EC]
    const unsigned char* __restrict__ dropped,  // [T] bool
    float* __restrict__ out)                    // [T, D]
{
    const int tid  = threadIdx.x;
    const int eng  = tid >> 7;                  // 0..3: row engine
    const int lane = tid & 127;
    const int bid  = blockIdx.x;

    // Prefetch both iterations' scalars (independent loads, issue together).
    const int i0 = bid * 8 + eng;
    const int i1 = i0 + 4;
    const int r0 = __ldg(scatter_idx + i0);
    const int r1 = __ldg(scatter_idx + i1);

    int  t0 = 0, t1 = 0;
    bool d0 = false, d1 = false;
    if (bid < T_BLKS) {
        t0 = bid * 8 + eng;
        t1 = t0 + 4;
        d0 = dropped[t0] != 0;
        d1 = dropped[t1] != 0;
    }

    // ---- Scatter iteration 0 ----
    if (r0 < T_TOK) {
        const float factor = __ldg(route_prob_max + r0);
        const float4* __restrict__ src4 =
            reinterpret_cast<const float4*>(expert_outputs + (size_t)i0 * D_DIM);
        float4* __restrict__ dst4 =
            reinterpret_cast<float4*>(out + (size_t)r0 * D_DIM);

        float4 v0 = __ldcs(&src4[lane]);
        float4 v1 = __ldcs(&src4[lane + 128]);
        float4 v2 = __ldcs(&src4[lane + 256]);
        float4 v3 = __ldcs(&src4[lane + 384]);

        v0.x *= factor; v0.y *= factor; v0.z *= factor; v0.w *= factor;
        v1.x *= factor; v1.y *= factor; v1.z *= factor; v1.w *= factor;
        v2.x *= factor; v2.y *= factor; v2.z *= factor; v2.w *= factor;
        v3.x *= factor; v3.y *= factor; v3.z *= factor; v3.w *= factor;

        __stcs(&dst4[lane],       v0);
        __stcs(&dst4[lane + 128], v1);
        __stcs(&dst4[lane + 256], v2);
        __stcs(&dst4[lane + 384], v3);
    }

    // ---- Scatter iteration 1 (chain already resolved) ----
    if (r1 < T_TOK) {
        const float factor = __ldg(route_prob_max + r1);
        const float4* __restrict__ src4 =
            reinterpret_cast<const float4*>(expert_outputs + (size_t)i1 * D_DIM);
        float4* __restrict__ dst4 =
            reinterpret_cast<float4*>(out + (size_t)r1 * D_DIM);

        float4 v0 = __ldcs(&src4[lane]);
        float4 v1 = __ldcs(&src4[lane + 128]);
        float4 v2 = __ldcs(&src4[lane + 256]);
        float4 v3 = __ldcs(&src4[lane + 384]);

        v0.x *= factor; v0.y *= factor; v0.z *= factor; v0.w *= factor;
        v1.x *= factor; v1.y *= factor; v1.z *= factor; v1.w *= factor;
        v2.x *= factor; v2.y *= factor; v2.z *= factor; v2.w *= factor;
        v3.x *= factor; v3.y *= factor; v3.z *= factor; v3.w *= factor;

        __stcs(&dst4[lane],       v0);
        __stcs(&dst4[lane + 128], v1);
        __stcs(&dst4[lane + 256], v2);
        __stcs(&dst4[lane + 384], v3);
    }

    // ---- Fallback: dropped tokens pass x through (factor 1) ----
    if (d0) {
        const float4* __restrict__ src4 =
            reinterpret_cast<const float4*>(x + (size_t)t0 * D_DIM);
        float4* __restrict__ dst4 =
            reinterpret_cast<float4*>(out + (size_t)t0 * D_DIM);
        #pragma unroll
        for (int k = 0; k < 4; k++)
            __stcs(&dst4[lane + k * 128], __ldcs(&src4[lane + k * 128]));
    }
    if (d1) {
        const float4* __restrict__ src4 =
            reinterpret_cast<const float4*>(x + (size_t)t1 * D_DIM);
        float4* __restrict__ dst4 =
            reinterpret_cast<float4*>(out + (size_t)t1 * D_DIM);
        #pragma unroll
        for (int k = 0; k < 4; k++)
            __stcs(&dst4[lane + k * 128], __ldcs(&src4[lane + k * 128]));
    }
}

extern "C" void kernel_launch(void* const* d_in, const int* in_sizes, int n_in,
                              void* d_out, int out_size) {
    const float*         expert_outputs = (const float*)d_in[0];
    const float*         x              = (const float*)d_in[1];
    const float*         route_prob_max = (const float*)d_in[2];
    const int*           scatter_idx    = (const int*)d_in[3];
    const unsigned char* dropped        = (const unsigned char*)d_in[4];
    float* out = (float*)d_out;

    moe_scatter_kernel<<<EC_BLKS, 512>>>(
        expert_outputs, x, route_prob_max, scatter_idx, dropped, out);
}

// round 14
// speedup vs baseline: 1.0464x; 1.0464x over previous
#include <cuda_runtime.h>
#include <cstdint>

// Problem constants (fixed by the reference):
//   B=4, S=4096, D=2048, E=8, T=B*S=16384, C=T/E*1.25=2560, EC=E*C=20480
#define D_DIM    2048
#define T_TOK    16384
#define EC_ROWS  20480
#define EC_QUADS (EC_ROWS / 4)   // 5120 blocks, 4 expert slots each
#define T_QUADS  (T_TOK / 4)     // first 4096 blocks also cover 4 tokens' fallback

// FINAL FORM (measured best across 13 rounds): single-launch scatter,
// 512-thread blocks = 4 row-engines of 128 lanes x 4 float4. Each block
// handles 4 expert slots (skipping padding slots with scatter_idx == T);
// the first T_QUADS blocks also handle the x-fallback for 4 tokens (row
// copied only if dropped). Writer sets are disjoint (kept XOR dropped) and
// cover every output row, so one kernel with no scratch and no prep pass
// computes the full result. Streaming cache hints: zero reuse workload.
// Achieves ~6.9 TB/s effective (~86% of HBM spec) — at the LTS ceiling.
__global__ __launch_bounds__(512) void moe_scatter_kernel(
    const float* __restrict__ expert_outputs,   // [EC, D]
    const float* __restrict__ x,                // [T, D]
    const float* __restrict__ route_prob_max,   // [T]
    const int*   __restrict__ scatter_idx,      // [EC]
    const unsigned char* __restrict__ dropped,  // [T] bool
    float* __restrict__ out)                    // [T, D]
{
    const int tid  = threadIdx.x;
    const int quad = tid >> 7;                  // 0..3: which row of the quad
    const int lane = tid & 127;
    const int bid  = blockIdx.x;

    // ---- Scatter section: expert slot -> token row ----
    {
        const int i = bid * 4 + quad;           // expert slot
        const int r = __ldg(scatter_idx + i);
        if (r < T_TOK) {
            const float factor = __ldg(route_prob_max + r);  // overlaps row loads
            const float4* __restrict__ src4 =
                reinterpret_cast<const float4*>(expert_outputs + (size_t)i * D_DIM);
            float4* __restrict__ dst4 =
                reinterpret_cast<float4*>(out + (size_t)r * D_DIM);

            float4 v0 = __ldcs(&src4[lane]);
            float4 v1 = __ldcs(&src4[lane + 128]);
            float4 v2 = __ldcs(&src4[lane + 256]);
            float4 v3 = __ldcs(&src4[lane + 384]);

            v0.x *= factor; v0.y *= factor; v0.z *= factor; v0.w *= factor;
            v1.x *= factor; v1.y *= factor; v1.z *= factor; v1.w *= factor;
            v2.x *= factor; v2.y *= factor; v2.z *= factor; v2.w *= factor;
            v3.x *= factor; v3.y *= factor; v3.z *= factor; v3.w *= factor;

            __stcs(&dst4[lane],       v0);
            __stcs(&dst4[lane + 128], v1);
            __stcs(&dst4[lane + 256], v2);
            __stcs(&dst4[lane + 384], v3);
        }
    }

    // ---- Fallback section: dropped tokens pass x through (factor 1) ----
    if (bid < T_QUADS) {
        const int t = bid * 4 + quad;
        if (dropped[t]) {
            const float4* __restrict__ src4 =
                reinterpret_cast<const float4*>(x + (size_t)t * D_DIM);
            float4* __restrict__ dst4 =
                reinterpret_cast<float4*>(out + (size_t)t * D_DIM);

            float4 v0 = __ldcs(&src4[lane]);
            float4 v1 = __ldcs(&src4[lane + 128]);
            float4 v2 = __ldcs(&src4[lane + 256]);
            float4 v3 = __ldcs(&src4[lane + 384]);

            __stcs(&dst4[lane],       v0);
            __stcs(&dst4[lane + 128], v1);
            __stcs(&dst4[lane + 256], v2);
            __stcs(&dst4[lane + 384], v3);
        }
    }
}

extern "C" void kernel_launch(void* const* d_in, const int* in_sizes, int n_in,
                              void* d_out, int out_size) {
    const float*         expert_outputs = (const float*)d_in[0];
    const float*         x              = (const float*)d_in[1];
    const float*         route_prob_max = (const float*)d_in[2];
    const int*           scatter_idx    = (const int*)d_in[3];
    const unsigned char* dropped        = (const unsigned char*)d_in[4];
    float* out = (float*)d_out;

    moe_scatter_kernel<<<EC_QUADS, 512>>>(
        expert_outputs, x, route_prob_max, scatter_idx, dropped, out);
}